// round 14
// baseline (speedup 1.0000x reference)
#include <cuda_runtime.h>
#include <cuda_fp16.h>
#include <mma.h>
#include <math.h>

using namespace nvcuda;

#define NN    4096
#define INF_  512
#define HID   8
#define OUTF  256
#define MAXD  128

#define H2REF(u) (*(__half2*)&(u))

// ---------------- scratch (static device globals) ---------------------------
__device__ int    g_deg[NN];
__device__ int    g_nbr[NN * MAXD];
__device__ float  g_phu[NN * HID];
__device__ float  g_e1[NN];
__device__ float  g_qu[NN];
__device__ float  g_e2[NN];
__device__ int    g_mask1[NN];
__device__ __half g_xh[NN * INF_];
__device__ __half g_v [NN * OUTF];    // x @ W_A
__device__ __half g_u [NN * OUTF];    // x @ W_C
__device__ __half g_z1[NN * OUTF];    // A @ u
__device__ __half g_z2[NN * OUTF];    // A^2 @ u
__device__ __half g_WhA[INF_ * OUTF];
__device__ __half g_WhC[INF_ * OUTF];

// ---- fused prelude: build nbr lists | x->fp16 | h=x@W1 chain | W->fp16 -----
__global__ void k_prelude(const float* __restrict__ adj, const float* __restrict__ x,
                          const float* __restrict__ W1, const float* __restrict__ a1,
                          const float* __restrict__ Wsgc) {
    int b = blockIdx.x;
    int t = threadIdx.x;          // 256

    if (b < 4096) {
        int row = b;
        const float4* ar = (const float4*)(adj + (size_t)row * NN);
        float4 v[4];
        int cnt = 0;
#pragma unroll
        for (int i = 0; i < 4; i++) {
            v[i] = ar[t + i * 256];
            cnt += (v[i].x != 0.f) + (v[i].y != 0.f) + (v[i].z != 0.f) + (v[i].w != 0.f);
        }
        __shared__ int sc[256];
        sc[t] = cnt;
        __syncthreads();
        for (int d = 1; d < 256; d <<= 1) {
            int val = (t >= d) ? sc[t - d] : 0;
            __syncthreads();
            if (t >= d) sc[t] += val;
            __syncthreads();
        }
        int pos   = sc[t] - cnt;
        int total = sc[255];
        int* nb = g_nbr + (size_t)row * MAXD;
#pragma unroll
        for (int i = 0; i < 4; i++) {
            int base = (t + i * 256) * 4;
            if (v[i].x != 0.f) { if (pos < MAXD) nb[pos] = base + 0; pos++; }
            if (v[i].y != 0.f) { if (pos < MAXD) nb[pos] = base + 1; pos++; }
            if (v[i].z != 0.f) { if (pos < MAXD) nb[pos] = base + 2; pos++; }
            if (v[i].w != 0.f) { if (pos < MAXD) nb[pos] = base + 3; pos++; }
        }
        if (t == 0) g_deg[row] = total < MAXD ? total : MAXD;
    } else if (b < 6144) {
        int i = (b - 4096) * 256 + t;
        float4 v = ((const float4*)x)[i];
        __half2 lo = __floats2half2_rn(v.x, v.y);
        __half2 hi = __floats2half2_rn(v.z, v.w);
        uint2 packed;
        packed.x = *(unsigned*)&lo;
        packed.y = *(unsigned*)&hi;
        ((uint2*)g_xh)[i] = packed;
    } else if (b < 6656) {
        int lane = t & 31;
        int row  = (b - 6144) * 8 + (t >> 5);
        const float* xr = x + (size_t)row * INF_;
        float acc[HID];
#pragma unroll
        for (int f = 0; f < HID; f++) acc[f] = 0.f;
        for (int k = lane; k < INF_; k += 32) {
            float xv = xr[k];
            float4 wA = *(const float4*)(W1 + k * HID);
            float4 wB = *(const float4*)(W1 + k * HID + 4);
            acc[0] += xv * wA.x; acc[1] += xv * wA.y; acc[2] += xv * wA.z; acc[3] += xv * wA.w;
            acc[4] += xv * wB.x; acc[5] += xv * wB.y; acc[6] += xv * wB.z; acc[7] += xv * wB.w;
        }
#pragma unroll
        for (int f = 0; f < HID; f++)
            for (int o = 16; o; o >>= 1) acc[f] += __shfl_xor_sync(0xffffffffu, acc[f], o);
        if (lane == 0) {
            float d = 0.f;
#pragma unroll
            for (int f = 0; f < HID; f++) d += acc[f] * a1[HID + f];
            float e1 = expf(d);
            g_e1[row] = e1;
#pragma unroll
            for (int f = 0; f < HID; f++) g_phu[row * HID + f] = e1 * acc[f];
        }
    } else {
        int which = (b >= 6784);
        int base  = which ? 6784 : 6656;
        const float* src = Wsgc + (which ? (size_t)1024 * OUTF : 0);
        __half* dst = which ? g_WhC : g_WhA;
        int i = (b - base) * 256 + t;
        float4 v = ((const float4*)src)[i];
        __half2 lo = __floats2half2_rn(v.x, v.y);
        __half2 hi = __floats2half2_rn(v.z, v.w);
        uint2 packed;
        packed.x = *(unsigned*)&lo;
        packed.y = *(unsigned*)&hi;
        ((uint2*)dst)[i] = packed;
    }
}

// ---- block-redundant sum of 4096 floats (deterministic order) --------------
__device__ __forceinline__ float block_sum4096(const float* v, int t) {
    __shared__ float sred[8];
    __shared__ float sbc;
    float s = 0.f;
    const float4* v4 = (const float4*)v;
#pragma unroll
    for (int i = 0; i < 4; i++) {
        float4 a = v4[t + i * 256];
        s += (a.x + a.y) + (a.z + a.w);
    }
    for (int o = 16; o; o >>= 1) s += __shfl_xor_sync(0xffffffffu, s, o);
    if ((t & 31) == 0) sred[t >> 5] = s;
    __syncthreads();
    if (t < 32) {
        float r = (t < 8) ? sred[t] : 0.f;
        for (int o = 4; o; o >>= 1) r += __shfl_xor_sync(0xffffffffu, r, o);
        if (t == 0) sbc = r;
    }
    __syncthreads();
    return sbc;
}

// ---- gat1 body -------------------------------------------------------------
__device__ __forceinline__ void gat1_body(int blk, const float* __restrict__ W2,
                                          const float* __restrict__ a2) {
    int t    = threadIdx.x;
    float S1 = block_sum4096(g_e1, t);

    int lane = t & 31;
    int row  = blk * 8 + (t >> 5);
    int deg  = g_deg[row];
    const int* nb = g_nbr + (size_t)row * MAXD;

    float acc[HID];
#pragma unroll
    for (int f = 0; f < HID; f++) acc[f] = 0.f;

    for (int k = lane; k < deg; k += 32) {
        int j = nb[k];
        float4 A = *(const float4*)(g_phu + j * HID);
        float4 B = *(const float4*)(g_phu + j * HID + 4);
        acc[0] += A.x; acc[1] += A.y; acc[2] += A.z; acc[3] += A.w;
        acc[4] += B.x; acc[5] += B.y; acc[6] += B.z; acc[7] += B.w;
    }
#pragma unroll
    for (int f = 0; f < HID; f++)
        for (int o = 16; o; o >>= 1) acc[f] += __shfl_xor_sync(0xffffffffu, acc[f], o);

    if (lane == 0) {
        float invS = 1.f / S1;
        float h2 = 0.f;
#pragma unroll
        for (int f = 0; f < HID; f++) {
            float v = acc[f] * invS;
            v = v > 0.f ? v : (expf(v) - 1.f);   // elu
            h2 += v * W2[f];
        }
        float e2 = expf(h2 * a2[1]);
        g_e2[row] = e2;
        g_qu[row] = e2 * h2;
    }
}

// ---- mask body -------------------------------------------------------------
__device__ __forceinline__ void mask_body(int blk) {
    int t    = threadIdx.x;
    float S2 = block_sum4096(g_e2, t);

    int lane = t & 31;
    int row  = blk * 8 + (t >> 5);
    int deg  = g_deg[row];
    const int* nb = g_nbr + (size_t)row * MAXD;

    float s = 0.f;
    for (int k = lane; k < deg; k += 32) s += g_qu[nb[k]];
    for (int o = 16; o; o >>= 1) s += __shfl_xor_sync(0xffffffffu, s, o);

    if (lane == 0) {
        float s2 = s / S2;
        float sc = s2 > 0.f ? s2 : (expf(s2) - 1.f);   // elu
        g_mask1[row] = (sc > 0.7f) ? 1 : 0;
    }
}

// ---- dense GEMM body: dst[4096x256] = xh @ Wh (fp16 out, fp32 acc) ---------
#define GLDA_S 72
#define GLDB_S 136
#define GLDS_F 132

__device__ __forceinline__ void gemm_dense(int which, int bx, int by) {
    __shared__ __align__(16) char buf[64 * GLDS_F * 4];

    __half* sA = (__half*)buf;
    __half* sB = (__half*)(buf + 64 * GLDA_S * 2);
    float*  stage = (float*)buf;

    const __half* W   = which ? g_WhC : g_WhA;
    __half*       dst = which ? g_u   : g_v;
    int rbase = bx * 64;
    int cb    = by * 128;

    int t = threadIdx.x;   // 256
    int warp = t >> 5;
    int wrow = warp & 3;
    int wcol = warp >> 2;

    const __half* aSrc = g_xh + (size_t)(rbase + (t >> 2)) * INF_;
    int apart = t & 3;

    wmma::fragment<wmma::accumulator, 16, 16, 16, float> cfr[4];
#pragma unroll
    for (int j = 0; j < 4; j++) wmma::fill_fragment(cfr[j], 0.f);

    for (int kc = 0; kc < INF_; kc += 64) {
#pragma unroll
        for (int u = 0; u < 2; u++) {
            int chunk = apart * 2 + u;
            uint4 v = *(const uint4*)(aSrc + kc + chunk * 8);
            *(uint4*)(sA + (t >> 2) * GLDA_S + chunk * 8) = v;
        }
#pragma unroll
        for (int v4 = 0; v4 < 4; v4++) {
            int idx = v4 * 256 + t;
            int krow = idx >> 4, chunk = idx & 15;
            uint4 v = *(const uint4*)(W + (size_t)(kc + krow) * OUTF + cb + chunk * 8);
            *(uint4*)(sB + krow * GLDB_S + chunk * 8) = v;
        }
        __syncthreads();

#pragma unroll
        for (int ks = 0; ks < 4; ks++) {
            wmma::fragment<wmma::matrix_a, 16, 16, 16, __half, wmma::row_major> afr;
            wmma::load_matrix_sync(afr, sA + wrow * 16 * GLDA_S + ks * 16, GLDA_S);
#pragma unroll
            for (int j = 0; j < 4; j++) {
                wmma::fragment<wmma::matrix_b, 16, 16, 16, __half, wmma::row_major> bfr;
                wmma::load_matrix_sync(bfr, sB + ks * 16 * GLDB_S + wcol * 64 + j * 16, GLDB_S);
                wmma::mma_sync(cfr[j], afr, bfr, cfr[j]);
            }
        }
        __syncthreads();
    }

#pragma unroll
    for (int j = 0; j < 4; j++)
        wmma::store_matrix_sync(stage + wrow * 16 * GLDS_F + wcol * 64 + j * 16,
                                cfr[j], GLDS_F, wmma::mem_row_major);
    __syncthreads();

#pragma unroll
    for (int w = 0; w < 8; w++) {
        int idx = w * 256 + t;
        int rl = idx >> 5, chunk = idx & 31;
        int col = chunk * 4;
        float4 v = *(const float4*)(stage + rl * GLDS_F + col);
        __half2 h0 = __floats2half2_rn(v.x, v.y);
        __half2 h1 = __floats2half2_rn(v.z, v.w);
        uint2 p;
        p.x = *(unsigned*)&h0;
        p.y = *(unsigned*)&h1;
        *(uint2*)(dst + (size_t)(rbase + rl) * OUTF + cb + col) = p;
    }
}

// ---- gather core (64-col quarter): fp16 pair-tree, fp32 across groups ------
// Each thread owns 2 columns (one __half2). Same per-column order as R12.
__device__ __forceinline__ void gather_accum64(const __half* __restrict__ src,
                                               const int* __restrict__ nb,
                                               int deg, int c, float* acc) {
    int k = 0;
    for (; k + 8 <= deg; k += 8) {
        int j[8];
#pragma unroll
        for (int u = 0; u < 8; u++) j[u] = __ldg(nb + k + u);
        unsigned r[8];
#pragma unroll
        for (int u = 0; u < 8; u++)
            r[u] = *(const unsigned*)(src + (size_t)j[u] * OUTF + c);
        __half2 s01 = __hadd2(H2REF(r[0]), H2REF(r[1]));
        __half2 s23 = __hadd2(H2REF(r[2]), H2REF(r[3]));
        __half2 s45 = __hadd2(H2REF(r[4]), H2REF(r[5]));
        __half2 s67 = __hadd2(H2REF(r[6]), H2REF(r[7]));
        __half2 t0  = __hadd2(s01, s23);
        __half2 t1  = __hadd2(s45, s67);
        float2 f;
        f = __half22float2(t0); acc[0] += f.x; acc[1] += f.y;
        f = __half22float2(t1); acc[0] += f.x; acc[1] += f.y;
    }
    for (; k < deg; k++) {
        int j = __ldg(nb + k);
        unsigned rv = *(const unsigned*)(src + (size_t)j * OUTF + c);
        float2 f = __half22float2(H2REF(rv));
        acc[0] += f.x; acc[1] += f.y;
    }
}

// ---- SpMM 64-col quarter: warp per (row, quarter) --------------------------
// blk in [0,2048): unit = blk*8+wid covers 4096 rows x 4 quarters
__device__ __forceinline__ void spmm64(const __half* __restrict__ src,
                                       __half* __restrict__ dst, int blk) {
    int wid  = threadIdx.x >> 5;
    int lane = threadIdx.x & 31;
    int unit = blk * 8 + wid;
    int row  = unit >> 2;
    int q    = unit & 3;
    int deg  = g_deg[row];
    const int* __restrict__ nb = g_nbr + (size_t)row * MAXD;

    int c = q * 64 + (lane << 1);     // 32 thr * 2 halves = 64 cols
    float acc[2] = {0.f, 0.f};
    gather_accum64(src, nb, deg, c, acc);

    __half2 h = __floats2half2_rn(acc[0], acc[1]);
    *(unsigned*)(dst + (size_t)row * OUTF + c) = *(unsigned*)&h;
}

// ---- routed-output body (64-col quarter) -----------------------------------
__device__ __forceinline__ void out_body64(int blk, int sel,
                                           const float* __restrict__ bias,
                                           float* __restrict__ out) {
    int wid  = threadIdx.x >> 5;
    int lane = threadIdx.x & 31;
    int unit = blk * 8 + wid;
    int row  = unit >> 2;
    int q    = unit & 3;
    if (g_mask1[row] != sel) return;
    int deg  = g_deg[row];
    const int* __restrict__ nb = g_nbr + (size_t)row * MAXD;
    const __half* __restrict__ src = sel ? g_v : g_z2;

    int c = q * 64 + (lane << 1);
    float acc[2] = {0.f, 0.f};
    gather_accum64(src, nb, deg, c, acc);

    float2 b0 = *(const float2*)(bias + c);
    *(float2*)(out + (size_t)row * OUTF + c) =
        make_float2(acc[0] + b0.x, acc[1] + b0.y);
}

// ---- L2: dense GEMMs u,v [0,256) | gat1 [256,768) --------------------------
__global__ void k_gemm_gat1(const float* __restrict__ W2, const float* __restrict__ a2) {
    int b = blockIdx.x;
    if (b < 256) {
        int which = b >> 7;
        int tile  = b & 127;
        gemm_dense(which, tile >> 1, tile & 1);
    } else {
        gat1_body(b - 256, W2, a2);
    }
}

// ---- L3: z1 = A@u [0,2048) | mask [2048,2560) ------------------------------
__global__ void k_z1_mask() {
    int b = blockIdx.x;
    if (b < 2048) spmm64(g_u, g_z1, b);
    else          mask_body(b - 2048);
}

// ---- L4: z2 = A@z1 [0,2048) | out(mask1) [2048,4096) -----------------------
__global__ void k_z2_out1(const float* __restrict__ bias, float* __restrict__ out) {
    int b = blockIdx.x;
    if (b < 2048) spmm64(g_z1, g_z2, b);
    else          out_body64(b - 2048, 1, bias, out);
}

// ---- L5: out(mask0) (needs z2) ---------------------------------------------
__global__ void k_out0(const float* __restrict__ bias, float* __restrict__ out) {
    out_body64(blockIdx.x, 0, bias, out);
}

// ---------------- launcher --------------------------------------------------
extern "C" void kernel_launch(void* const* d_in, const int* in_sizes, int n_in,
                              void* d_out, int out_size) {
    const float* x    = (const float*)d_in[0];
    const float* adj  = (const float*)d_in[1];
    const float* W1   = (const float*)d_in[2];
    const float* a1   = (const float*)d_in[3];
    const float* W2   = (const float*)d_in[4];
    const float* a2   = (const float*)d_in[5];
    const float* Wsgc = (const float*)d_in[6];
    const float* bsgc = (const float*)d_in[7];
    float* out = (float*)d_out;

    k_prelude<<<6912, 256>>>(adj, x, W1, a1, Wsgc);
    k_gemm_gat1<<<768, 256>>>(W2, a2);          // v=x@WA, u=x@WC || gat1
    k_z1_mask<<<2560, 256>>>();                 // z1 = A@u || mask
    k_z2_out1<<<4096, 256>>>(bsgc, out);        // z2 = A@z1 || out(mask1)
    k_out0<<<2048, 256>>>(bsgc, out);           // out(mask0)
}

// round 15
// speedup vs baseline: 1.6023x; 1.6023x over previous
#include <cuda_runtime.h>
#include <cuda_fp16.h>
#include <mma.h>
#include <math.h>

using namespace nvcuda;

#define NN    4096
#define INF_  512
#define HID   8
#define OUTF  256
#define MAXD  128

#define H2REF(u) (*(__half2*)&(u))

// ---------------- scratch (static device globals) ---------------------------
__device__ int    g_deg[NN];
__device__ int    g_nbr[NN * MAXD];
__device__ int    g_perm[NN];         // rows in descending-degree order
__device__ float  g_phu[NN * HID];
__device__ float  g_e1[NN];
__device__ float  g_qu[NN];
__device__ float  g_e2[NN];
__device__ int    g_mask1[NN];
__device__ __half g_xh[NN * INF_];
__device__ __half g_v [NN * OUTF];    // x @ W_A
__device__ __half g_u [NN * OUTF];    // x @ W_C
__device__ __half g_z1[NN * OUTF];    // A @ u
__device__ __half g_z2[NN * OUTF];    // A^2 @ u
__device__ __half g_WhA[INF_ * OUTF];
__device__ __half g_WhC[INF_ * OUTF];

// ---- fused prelude: build nbr lists | x->fp16 | h=x@W1 chain | W->fp16 -----
__global__ void k_prelude(const float* __restrict__ adj, const float* __restrict__ x,
                          const float* __restrict__ W1, const float* __restrict__ a1,
                          const float* __restrict__ Wsgc) {
    int b = blockIdx.x;
    int t = threadIdx.x;          // 256

    if (b < 4096) {
        int row = b;
        const float4* ar = (const float4*)(adj + (size_t)row * NN);
        float4 v[4];
        int cnt = 0;
#pragma unroll
        for (int i = 0; i < 4; i++) {
            v[i] = ar[t + i * 256];
            cnt += (v[i].x != 0.f) + (v[i].y != 0.f) + (v[i].z != 0.f) + (v[i].w != 0.f);
        }
        __shared__ int sc[256];
        sc[t] = cnt;
        __syncthreads();
        for (int d = 1; d < 256; d <<= 1) {
            int val = (t >= d) ? sc[t - d] : 0;
            __syncthreads();
            if (t >= d) sc[t] += val;
            __syncthreads();
        }
        int pos   = sc[t] - cnt;
        int total = sc[255];
        int* nb = g_nbr + (size_t)row * MAXD;
#pragma unroll
        for (int i = 0; i < 4; i++) {
            int base = (t + i * 256) * 4;
            if (v[i].x != 0.f) { if (pos < MAXD) nb[pos] = base + 0; pos++; }
            if (v[i].y != 0.f) { if (pos < MAXD) nb[pos] = base + 1; pos++; }
            if (v[i].z != 0.f) { if (pos < MAXD) nb[pos] = base + 2; pos++; }
            if (v[i].w != 0.f) { if (pos < MAXD) nb[pos] = base + 3; pos++; }
        }
        if (t == 0) g_deg[row] = total < MAXD ? total : MAXD;
    } else if (b < 6144) {
        int i = (b - 4096) * 256 + t;
        float4 v = ((const float4*)x)[i];
        __half2 lo = __floats2half2_rn(v.x, v.y);
        __half2 hi = __floats2half2_rn(v.z, v.w);
        uint2 packed;
        packed.x = *(unsigned*)&lo;
        packed.y = *(unsigned*)&hi;
        ((uint2*)g_xh)[i] = packed;
    } else if (b < 6656) {
        int lane = t & 31;
        int row  = (b - 6144) * 8 + (t >> 5);
        const float* xr = x + (size_t)row * INF_;
        float acc[HID];
#pragma unroll
        for (int f = 0; f < HID; f++) acc[f] = 0.f;
        for (int k = lane; k < INF_; k += 32) {
            float xv = xr[k];
            float4 wA = *(const float4*)(W1 + k * HID);
            float4 wB = *(const float4*)(W1 + k * HID + 4);
            acc[0] += xv * wA.x; acc[1] += xv * wA.y; acc[2] += xv * wA.z; acc[3] += xv * wA.w;
            acc[4] += xv * wB.x; acc[5] += xv * wB.y; acc[6] += xv * wB.z; acc[7] += xv * wB.w;
        }
#pragma unroll
        for (int f = 0; f < HID; f++)
            for (int o = 16; o; o >>= 1) acc[f] += __shfl_xor_sync(0xffffffffu, acc[f], o);
        if (lane == 0) {
            float d = 0.f;
#pragma unroll
            for (int f = 0; f < HID; f++) d += acc[f] * a1[HID + f];
            float e1 = expf(d);
            g_e1[row] = e1;
#pragma unroll
            for (int f = 0; f < HID; f++) g_phu[row * HID + f] = e1 * acc[f];
        }
    } else {
        int which = (b >= 6784);
        int base  = which ? 6784 : 6656;
        const float* src = Wsgc + (which ? (size_t)1024 * OUTF : 0);
        __half* dst = which ? g_WhC : g_WhA;
        int i = (b - base) * 256 + t;
        float4 v = ((const float4*)src)[i];
        __half2 lo = __floats2half2_rn(v.x, v.y);
        __half2 hi = __floats2half2_rn(v.z, v.w);
        uint2 packed;
        packed.x = *(unsigned*)&lo;
        packed.y = *(unsigned*)&hi;
        ((uint2*)dst)[i] = packed;
    }
}

// ---- block-redundant sum of 4096 floats (deterministic order) --------------
__device__ __forceinline__ float block_sum4096(const float* v, int t) {
    __shared__ float sred[8];
    __shared__ float sbc;
    float s = 0.f;
    const float4* v4 = (const float4*)v;
#pragma unroll
    for (int i = 0; i < 4; i++) {
        float4 a = v4[t + i * 256];
        s += (a.x + a.y) + (a.z + a.w);
    }
    for (int o = 16; o; o >>= 1) s += __shfl_xor_sync(0xffffffffu, s, o);
    if ((t & 31) == 0) sred[t >> 5] = s;
    __syncthreads();
    if (t < 32) {
        float r = (t < 8) ? sred[t] : 0.f;
        for (int o = 4; o; o >>= 1) r += __shfl_xor_sync(0xffffffffu, r, o);
        if (t == 0) sbc = r;
    }
    __syncthreads();
    return sbc;
}

// ---- gat1 body -------------------------------------------------------------
__device__ __forceinline__ void gat1_body(int blk, const float* __restrict__ W2,
                                          const float* __restrict__ a2) {
    int t    = threadIdx.x;
    float S1 = block_sum4096(g_e1, t);

    int lane = t & 31;
    int row  = blk * 8 + (t >> 5);
    int deg  = g_deg[row];
    const int* nb = g_nbr + (size_t)row * MAXD;

    float acc[HID];
#pragma unroll
    for (int f = 0; f < HID; f++) acc[f] = 0.f;

    for (int k = lane; k < deg; k += 32) {
        int j = nb[k];
        float4 A = *(const float4*)(g_phu + j * HID);
        float4 B = *(const float4*)(g_phu + j * HID + 4);
        acc[0] += A.x; acc[1] += A.y; acc[2] += A.z; acc[3] += A.w;
        acc[4] += B.x; acc[5] += B.y; acc[6] += B.z; acc[7] += B.w;
    }
#pragma unroll
    for (int f = 0; f < HID; f++)
        for (int o = 16; o; o >>= 1) acc[f] += __shfl_xor_sync(0xffffffffu, acc[f], o);

    if (lane == 0) {
        float invS = 1.f / S1;
        float h2 = 0.f;
#pragma unroll
        for (int f = 0; f < HID; f++) {
            float v = acc[f] * invS;
            v = v > 0.f ? v : (expf(v) - 1.f);   // elu
            h2 += v * W2[f];
        }
        float e2 = expf(h2 * a2[1]);
        g_e2[row] = e2;
        g_qu[row] = e2 * h2;
    }
}

// ---- mask body -------------------------------------------------------------
__device__ __forceinline__ void mask_body(int blk) {
    int t    = threadIdx.x;
    float S2 = block_sum4096(g_e2, t);

    int lane = t & 31;
    int row  = blk * 8 + (t >> 5);
    int deg  = g_deg[row];
    const int* nb = g_nbr + (size_t)row * MAXD;

    float s = 0.f;
    for (int k = lane; k < deg; k += 32) s += g_qu[nb[k]];
    for (int o = 16; o; o >>= 1) s += __shfl_xor_sync(0xffffffffu, s, o);

    if (lane == 0) {
        float s2 = s / S2;
        float sc = s2 > 0.f ? s2 : (expf(s2) - 1.f);   // elu
        g_mask1[row] = (sc > 0.7f) ? 1 : 0;
    }
}

// ---- perm body: counting-sort rows by descending degree --------------------
// Only scheduling depends on perm; outputs are independent of order.
__device__ __forceinline__ void perm_body() {
    __shared__ int hist[MAXD + 1];
    __shared__ int off[MAXD + 1];
    int t = threadIdx.x;   // 256
    if (t <= MAXD) hist[t] = 0;
    __syncthreads();
    for (int r = t; r < NN; r += 256) atomicAdd(&hist[g_deg[r]], 1);
    __syncthreads();
    if (t == 0) {
        int s = 0;
        for (int d = MAXD; d >= 0; d--) { off[d] = s; s += hist[d]; }
    }
    __syncthreads();
    for (int r = t; r < NN; r += 256) {
        int pos = atomicAdd(&off[g_deg[r]], 1);
        g_perm[pos] = r;
    }
}

// ---- dense GEMM body: dst[4096x256] = xh @ Wh (fp16 out, fp32 acc) ---------
#define GLDA_S 72
#define GLDB_S 136
#define GLDS_F 132

__device__ __forceinline__ void gemm_dense(int which, int bx, int by) {
    __shared__ __align__(16) char buf[64 * GLDS_F * 4];

    __half* sA = (__half*)buf;
    __half* sB = (__half*)(buf + 64 * GLDA_S * 2);
    float*  stage = (float*)buf;

    const __half* W   = which ? g_WhC : g_WhA;
    __half*       dst = which ? g_u   : g_v;
    int rbase = bx * 64;
    int cb    = by * 128;

    int t = threadIdx.x;   // 256
    int warp = t >> 5;
    int wrow = warp & 3;
    int wcol = warp >> 2;

    const __half* aSrc = g_xh + (size_t)(rbase + (t >> 2)) * INF_;
    int apart = t & 3;

    wmma::fragment<wmma::accumulator, 16, 16, 16, float> cfr[4];
#pragma unroll
    for (int j = 0; j < 4; j++) wmma::fill_fragment(cfr[j], 0.f);

    for (int kc = 0; kc < INF_; kc += 64) {
#pragma unroll
        for (int u = 0; u < 2; u++) {
            int chunk = apart * 2 + u;
            uint4 v = *(const uint4*)(aSrc + kc + chunk * 8);
            *(uint4*)(sA + (t >> 2) * GLDA_S + chunk * 8) = v;
        }
#pragma unroll
        for (int v4 = 0; v4 < 4; v4++) {
            int idx = v4 * 256 + t;
            int krow = idx >> 4, chunk = idx & 15;
            uint4 v = *(const uint4*)(W + (size_t)(kc + krow) * OUTF + cb + chunk * 8);
            *(uint4*)(sB + krow * GLDB_S + chunk * 8) = v;
        }
        __syncthreads();

#pragma unroll
        for (int ks = 0; ks < 4; ks++) {
            wmma::fragment<wmma::matrix_a, 16, 16, 16, __half, wmma::row_major> afr;
            wmma::load_matrix_sync(afr, sA + wrow * 16 * GLDA_S + ks * 16, GLDA_S);
#pragma unroll
            for (int j = 0; j < 4; j++) {
                wmma::fragment<wmma::matrix_b, 16, 16, 16, __half, wmma::row_major> bfr;
                wmma::load_matrix_sync(bfr, sB + ks * 16 * GLDB_S + wcol * 64 + j * 16, GLDB_S);
                wmma::mma_sync(cfr[j], afr, bfr, cfr[j]);
            }
        }
        __syncthreads();
    }

#pragma unroll
    for (int j = 0; j < 4; j++)
        wmma::store_matrix_sync(stage + wrow * 16 * GLDS_F + wcol * 64 + j * 16,
                                cfr[j], GLDS_F, wmma::mem_row_major);
    __syncthreads();

#pragma unroll
    for (int w = 0; w < 8; w++) {
        int idx = w * 256 + t;
        int rl = idx >> 5, chunk = idx & 31;
        int col = chunk * 4;
        float4 v = *(const float4*)(stage + rl * GLDS_F + col);
        __half2 h0 = __floats2half2_rn(v.x, v.y);
        __half2 h1 = __floats2half2_rn(v.z, v.w);
        uint2 p;
        p.x = *(unsigned*)&h0;
        p.y = *(unsigned*)&h1;
        *(uint2*)(dst + (size_t)(rbase + rl) * OUTF + cb + col) = p;
    }
}

// ---- gather-sum core (R12): fp16 pair-tree, fp32 across groups -------------
__device__ __forceinline__ void gather_accum(const __half* __restrict__ src,
                                             const int* __restrict__ nb,
                                             int deg, int c, float* acc) {
    int k = 0;
    for (; k + 8 <= deg; k += 8) {
        int j[8];
#pragma unroll
        for (int u = 0; u < 8; u++) j[u] = __ldg(nb + k + u);
        uint2 r[8];
#pragma unroll
        for (int u = 0; u < 8; u++)
            r[u] = *(const uint2*)(src + (size_t)j[u] * OUTF + c);
        __half2 sx01 = __hadd2(H2REF(r[0].x), H2REF(r[1].x));
        __half2 sy01 = __hadd2(H2REF(r[0].y), H2REF(r[1].y));
        __half2 sx23 = __hadd2(H2REF(r[2].x), H2REF(r[3].x));
        __half2 sy23 = __hadd2(H2REF(r[2].y), H2REF(r[3].y));
        __half2 sx45 = __hadd2(H2REF(r[4].x), H2REF(r[5].x));
        __half2 sy45 = __hadd2(H2REF(r[4].y), H2REF(r[5].y));
        __half2 sx67 = __hadd2(H2REF(r[6].x), H2REF(r[7].x));
        __half2 sy67 = __hadd2(H2REF(r[6].y), H2REF(r[7].y));
        __half2 tx0 = __hadd2(sx01, sx23);
        __half2 ty0 = __hadd2(sy01, sy23);
        __half2 tx1 = __hadd2(sx45, sx67);
        __half2 ty1 = __hadd2(sy45, sy67);
        float2 f;
        f = __half22float2(tx0); acc[0] += f.x; acc[1] += f.y;
        f = __half22float2(ty0); acc[2] += f.x; acc[3] += f.y;
        f = __half22float2(tx1); acc[0] += f.x; acc[1] += f.y;
        f = __half22float2(ty1); acc[2] += f.x; acc[3] += f.y;
    }
    for (; k < deg; k++) {
        int j = __ldg(nb + k);
        uint2 rv = *(const uint2*)(src + (size_t)j * OUTF + c);
        float2 f0 = __half22float2(H2REF(rv.x));
        float2 f1 = __half22float2(H2REF(rv.y));
        acc[0] += f0.x; acc[1] += f0.y; acc[2] += f1.x; acc[3] += f1.y;
    }
}

// ---- SpMM 128-col half: warp per (row, col-half), degree-sorted rows -------
__device__ __forceinline__ void spmm128(const __half* __restrict__ src,
                                        __half* __restrict__ dst,
                                        int blk, int ch) {
    int wid  = threadIdx.x >> 5;
    int lane = threadIdx.x & 31;
    int row  = g_perm[blk * 8 + wid];
    int deg  = g_deg[row];
    const int* __restrict__ nb = g_nbr + (size_t)row * MAXD;

    int c = ch * 128 + (lane << 2);
    float acc[4] = {0.f, 0.f, 0.f, 0.f};
    gather_accum(src, nb, deg, c, acc);

    uint2 packed;
    __half2 h0 = __floats2half2_rn(acc[0], acc[1]);
    __half2 h1 = __floats2half2_rn(acc[2], acc[3]);
    packed.x = *(unsigned*)&h0;
    packed.y = *(unsigned*)&h1;
    *(uint2*)(dst + (size_t)row * OUTF + c) = packed;
}

// ---- routed-output body (degree-sorted rows) -------------------------------
__device__ __forceinline__ void out_body(int blk, int ch, int sel,
                                         const float* __restrict__ bias,
                                         float* __restrict__ out) {
    int wid  = threadIdx.x >> 5;
    int lane = threadIdx.x & 31;
    int row  = g_perm[blk * 8 + wid];
    if (g_mask1[row] != sel) return;
    int deg  = g_deg[row];
    const int* __restrict__ nb = g_nbr + (size_t)row * MAXD;
    const __half* __restrict__ src = sel ? g_v : g_z2;

    int c = ch * 128 + (lane << 2);
    float acc[4] = {0.f, 0.f, 0.f, 0.f};
    gather_accum(src, nb, deg, c, acc);

    float4 b0 = *(const float4*)(bias + c);
    *(float4*)(out + (size_t)row * OUTF + c) =
        make_float4(acc[0] + b0.x, acc[1] + b0.y, acc[2] + b0.z, acc[3] + b0.w);
}

// ---- L2: dense GEMMs u,v [0,256) | gat1 [256,768) | perm sort [768] --------
__global__ void k_gemm_gat1(const float* __restrict__ W2, const float* __restrict__ a2) {
    int b = blockIdx.x;
    if (b < 256) {
        int which = b >> 7;
        int tile  = b & 127;
        gemm_dense(which, tile >> 1, tile & 1);
    } else if (b < 768) {
        gat1_body(b - 256, W2, a2);
    } else {
        perm_body();
    }
}

// ---- L3: z1 = A@u [0,1024) | mask [1024,1536) ------------------------------
__global__ void k_z1_mask() {
    int b = blockIdx.x;
    if (b < 1024) spmm128(g_u, g_z1, b >> 1, b & 1);
    else          mask_body(b - 1024);
}

// ---- L4: z2 = A@z1 [0,1024) | out(mask1) [1024,2048) -----------------------
__global__ void k_z2_out1(const float* __restrict__ bias, float* __restrict__ out) {
    int b = blockIdx.x;
    if (b < 1024) spmm128(g_z1, g_z2, b >> 1, b & 1);
    else {
        int bb = b - 1024;
        out_body(bb >> 1, bb & 1, 1, bias, out);
    }
}

// ---- L5: out(mask0) (needs z2) ---------------------------------------------
__global__ void k_out0(const float* __restrict__ bias, float* __restrict__ out) {
    out_body(blockIdx.x, blockIdx.y, 0, bias, out);
}

// ---------------- launcher --------------------------------------------------
extern "C" void kernel_launch(void* const* d_in, const int* in_sizes, int n_in,
                              void* d_out, int out_size) {
    const float* x    = (const float*)d_in[0];
    const float* adj  = (const float*)d_in[1];
    const float* W1   = (const float*)d_in[2];
    const float* a1   = (const float*)d_in[3];
    const float* W2   = (const float*)d_in[4];
    const float* a2   = (const float*)d_in[5];
    const float* Wsgc = (const float*)d_in[6];
    const float* bsgc = (const float*)d_in[7];
    float* out = (float*)d_out;

    k_prelude<<<6912, 256>>>(adj, x, W1, a1, Wsgc);
    k_gemm_gat1<<<769, 256>>>(W2, a2);          // v,u GEMMs || gat1 || perm
    k_z1_mask<<<1536, 256>>>();                 // z1 = A@u || mask
    k_z2_out1<<<2048, 256>>>(bsgc, out);        // z2 = A@z1 || out(mask1)
    k_out0<<<dim3(512, 2), 256>>>(bsgc, out);   // out(mask0)
}

// round 16
// speedup vs baseline: 1.6121x; 1.0061x over previous
#include <cuda_runtime.h>
#include <cuda_fp16.h>
#include <mma.h>
#include <math.h>

using namespace nvcuda;

#define NN    4096
#define INF_  512
#define HID   8
#define OUTF  256
#define MAXD  128

#define H2REF(u) (*(__half2*)&(u))

// ---------------- scratch (static device globals) ---------------------------
__device__ int    g_deg[NN];
__device__ int    g_nbr[NN * MAXD];
__device__ int    g_perm[NN];         // rows in descending-degree order
__device__ float  g_phu[NN * HID];
__device__ float  g_e1[NN];
__device__ float  g_qu[NN];
__device__ float  g_e2[NN];
__device__ int    g_mask1[NN];
__device__ __half g_xh[NN * INF_];
__device__ __half g_v [NN * OUTF];    // x @ W_A
__device__ __half g_u [NN * OUTF];    // x @ W_C
__device__ __half g_z1[NN * OUTF];    // A @ u
__device__ __half g_z2[NN * OUTF];    // A^2 @ u
__device__ __half g_WhA[INF_ * OUTF];
__device__ __half g_WhC[INF_ * OUTF];

// ---- fused prelude: build nbr lists | x->fp16 | h=x@W1 chain | W->fp16 -----
__global__ void k_prelude(const float* __restrict__ adj, const float* __restrict__ x,
                          const float* __restrict__ W1, const float* __restrict__ a1,
                          const float* __restrict__ Wsgc) {
    int b = blockIdx.x;
    int t = threadIdx.x;          // 256

    if (b < 4096) {
        int row = b;
        const float4* ar = (const float4*)(adj + (size_t)row * NN);
        float4 v[4];
        int cnt = 0;
#pragma unroll
        for (int i = 0; i < 4; i++) {
            v[i] = ar[t + i * 256];
            cnt += (v[i].x != 0.f) + (v[i].y != 0.f) + (v[i].z != 0.f) + (v[i].w != 0.f);
        }
        __shared__ int sc[256];
        sc[t] = cnt;
        __syncthreads();
        for (int d = 1; d < 256; d <<= 1) {
            int val = (t >= d) ? sc[t - d] : 0;
            __syncthreads();
            if (t >= d) sc[t] += val;
            __syncthreads();
        }
        int pos   = sc[t] - cnt;
        int total = sc[255];
        int* nb = g_nbr + (size_t)row * MAXD;
#pragma unroll
        for (int i = 0; i < 4; i++) {
            int base = (t + i * 256) * 4;
            if (v[i].x != 0.f) { if (pos < MAXD) nb[pos] = base + 0; pos++; }
            if (v[i].y != 0.f) { if (pos < MAXD) nb[pos] = base + 1; pos++; }
            if (v[i].z != 0.f) { if (pos < MAXD) nb[pos] = base + 2; pos++; }
            if (v[i].w != 0.f) { if (pos < MAXD) nb[pos] = base + 3; pos++; }
        }
        if (t == 0) g_deg[row] = total < MAXD ? total : MAXD;
    } else if (b < 6144) {
        int i = (b - 4096) * 256 + t;
        float4 v = ((const float4*)x)[i];
        __half2 lo = __floats2half2_rn(v.x, v.y);
        __half2 hi = __floats2half2_rn(v.z, v.w);
        uint2 packed;
        packed.x = *(unsigned*)&lo;
        packed.y = *(unsigned*)&hi;
        ((uint2*)g_xh)[i] = packed;
    } else if (b < 6656) {
        int lane = t & 31;
        int row  = (b - 6144) * 8 + (t >> 5);
        const float* xr = x + (size_t)row * INF_;
        float acc[HID];
#pragma unroll
        for (int f = 0; f < HID; f++) acc[f] = 0.f;
        for (int k = lane; k < INF_; k += 32) {
            float xv = xr[k];
            float4 wA = *(const float4*)(W1 + k * HID);
            float4 wB = *(const float4*)(W1 + k * HID + 4);
            acc[0] += xv * wA.x; acc[1] += xv * wA.y; acc[2] += xv * wA.z; acc[3] += xv * wA.w;
            acc[4] += xv * wB.x; acc[5] += xv * wB.y; acc[6] += xv * wB.z; acc[7] += xv * wB.w;
        }
#pragma unroll
        for (int f = 0; f < HID; f++)
            for (int o = 16; o; o >>= 1) acc[f] += __shfl_xor_sync(0xffffffffu, acc[f], o);
        if (lane == 0) {
            float d = 0.f;
#pragma unroll
            for (int f = 0; f < HID; f++) d += acc[f] * a1[HID + f];
            float e1 = expf(d);
            g_e1[row] = e1;
#pragma unroll
            for (int f = 0; f < HID; f++) g_phu[row * HID + f] = e1 * acc[f];
        }
    } else {
        int which = (b >= 6784);
        int base  = which ? 6784 : 6656;
        const float* src = Wsgc + (which ? (size_t)1024 * OUTF : 0);
        __half* dst = which ? g_WhC : g_WhA;
        int i = (b - base) * 256 + t;
        float4 v = ((const float4*)src)[i];
        __half2 lo = __floats2half2_rn(v.x, v.y);
        __half2 hi = __floats2half2_rn(v.z, v.w);
        uint2 packed;
        packed.x = *(unsigned*)&lo;
        packed.y = *(unsigned*)&hi;
        ((uint2*)dst)[i] = packed;
    }
}

// ---- block-redundant sum of 4096 floats (deterministic order) --------------
__device__ __forceinline__ float block_sum4096(const float* v, int t) {
    __shared__ float sred[8];
    __shared__ float sbc;
    float s = 0.f;
    const float4* v4 = (const float4*)v;
#pragma unroll
    for (int i = 0; i < 4; i++) {
        float4 a = v4[t + i * 256];
        s += (a.x + a.y) + (a.z + a.w);
    }
    for (int o = 16; o; o >>= 1) s += __shfl_xor_sync(0xffffffffu, s, o);
    if ((t & 31) == 0) sred[t >> 5] = s;
    __syncthreads();
    if (t < 32) {
        float r = (t < 8) ? sred[t] : 0.f;
        for (int o = 4; o; o >>= 1) r += __shfl_xor_sync(0xffffffffu, r, o);
        if (t == 0) sbc = r;
    }
    __syncthreads();
    return sbc;
}

// ---- gat1 body -------------------------------------------------------------
__device__ __forceinline__ void gat1_body(int blk, const float* __restrict__ W2,
                                          const float* __restrict__ a2) {
    int t    = threadIdx.x;
    float S1 = block_sum4096(g_e1, t);

    int lane = t & 31;
    int row  = blk * 8 + (t >> 5);
    int deg  = g_deg[row];
    const int* nb = g_nbr + (size_t)row * MAXD;

    float acc[HID];
#pragma unroll
    for (int f = 0; f < HID; f++) acc[f] = 0.f;

    for (int k = lane; k < deg; k += 32) {
        int j = nb[k];
        float4 A = *(const float4*)(g_phu + j * HID);
        float4 B = *(const float4*)(g_phu + j * HID + 4);
        acc[0] += A.x; acc[1] += A.y; acc[2] += A.z; acc[3] += A.w;
        acc[4] += B.x; acc[5] += B.y; acc[6] += B.z; acc[7] += B.w;
    }
#pragma unroll
    for (int f = 0; f < HID; f++)
        for (int o = 16; o; o >>= 1) acc[f] += __shfl_xor_sync(0xffffffffu, acc[f], o);

    if (lane == 0) {
        float invS = 1.f / S1;
        float h2 = 0.f;
#pragma unroll
        for (int f = 0; f < HID; f++) {
            float v = acc[f] * invS;
            v = v > 0.f ? v : (expf(v) - 1.f);   // elu
            h2 += v * W2[f];
        }
        float e2 = expf(h2 * a2[1]);
        g_e2[row] = e2;
        g_qu[row] = e2 * h2;
    }
}

// ---- mask body -------------------------------------------------------------
__device__ __forceinline__ void mask_body(int blk) {
    int t    = threadIdx.x;
    float S2 = block_sum4096(g_e2, t);

    int lane = t & 31;
    int row  = blk * 8 + (t >> 5);
    int deg  = g_deg[row];
    const int* nb = g_nbr + (size_t)row * MAXD;

    float s = 0.f;
    for (int k = lane; k < deg; k += 32) s += g_qu[nb[k]];
    for (int o = 16; o; o >>= 1) s += __shfl_xor_sync(0xffffffffu, s, o);

    if (lane == 0) {
        float s2 = s / S2;
        float sc = s2 > 0.f ? s2 : (expf(s2) - 1.f);   // elu
        g_mask1[row] = (sc > 0.7f) ? 1 : 0;
    }
}

// ---- perm body: counting-sort rows by descending degree --------------------
__device__ __forceinline__ void perm_body() {
    __shared__ int hist[MAXD + 1];
    __shared__ int off[MAXD + 1];
    int t = threadIdx.x;   // 256
    if (t <= MAXD) hist[t] = 0;
    __syncthreads();
    for (int r = t; r < NN; r += 256) atomicAdd(&hist[g_deg[r]], 1);
    __syncthreads();
    if (t == 0) {
        int s = 0;
        for (int d = MAXD; d >= 0; d--) { off[d] = s; s += hist[d]; }
    }
    __syncthreads();
    for (int r = t; r < NN; r += 256) {
        int pos = atomicAdd(&off[g_deg[r]], 1);
        g_perm[pos] = r;
    }
}

// ---- dense GEMM body: dst[4096x256] = xh @ Wh (fp16 out, fp32 acc) ---------
#define GLDA_S 72
#define GLDB_S 136
#define GLDS_F 132

__device__ __forceinline__ void gemm_dense(int which, int bx, int by) {
    __shared__ __align__(16) char buf[64 * GLDS_F * 4];

    __half* sA = (__half*)buf;
    __half* sB = (__half*)(buf + 64 * GLDA_S * 2);
    float*  stage = (float*)buf;

    const __half* W   = which ? g_WhC : g_WhA;
    __half*       dst = which ? g_u   : g_v;
    int rbase = bx * 64;
    int cb    = by * 128;

    int t = threadIdx.x;   // 256
    int warp = t >> 5;
    int wrow = warp & 3;
    int wcol = warp >> 2;

    const __half* aSrc = g_xh + (size_t)(rbase + (t >> 2)) * INF_;
    int apart = t & 3;

    wmma::fragment<wmma::accumulator, 16, 16, 16, float> cfr[4];
#pragma unroll
    for (int j = 0; j < 4; j++) wmma::fill_fragment(cfr[j], 0.f);

    for (int kc = 0; kc < INF_; kc += 64) {
#pragma unroll
        for (int u = 0; u < 2; u++) {
            int chunk = apart * 2 + u;
            uint4 v = *(const uint4*)(aSrc + kc + chunk * 8);
            *(uint4*)(sA + (t >> 2) * GLDA_S + chunk * 8) = v;
        }
#pragma unroll
        for (int v4 = 0; v4 < 4; v4++) {
            int idx = v4 * 256 + t;
            int krow = idx >> 4, chunk = idx & 15;
            uint4 v = *(const uint4*)(W + (size_t)(kc + krow) * OUTF + cb + chunk * 8);
            *(uint4*)(sB + krow * GLDB_S + chunk * 8) = v;
        }
        __syncthreads();

#pragma unroll
        for (int ks = 0; ks < 4; ks++) {
            wmma::fragment<wmma::matrix_a, 16, 16, 16, __half, wmma::row_major> afr;
            wmma::load_matrix_sync(afr, sA + wrow * 16 * GLDA_S + ks * 16, GLDA_S);
#pragma unroll
            for (int j = 0; j < 4; j++) {
                wmma::fragment<wmma::matrix_b, 16, 16, 16, __half, wmma::row_major> bfr;
                wmma::load_matrix_sync(bfr, sB + ks * 16 * GLDB_S + wcol * 64 + j * 16, GLDB_S);
                wmma::mma_sync(cfr[j], afr, bfr, cfr[j]);
            }
        }
        __syncthreads();
    }

#pragma unroll
    for (int j = 0; j < 4; j++)
        wmma::store_matrix_sync(stage + wrow * 16 * GLDS_F + wcol * 64 + j * 16,
                                cfr[j], GLDS_F, wmma::mem_row_major);
    __syncthreads();

#pragma unroll
    for (int w = 0; w < 8; w++) {
        int idx = w * 256 + t;
        int rl = idx >> 5, chunk = idx & 31;
        int col = chunk * 4;
        float4 v = *(const float4*)(stage + rl * GLDS_F + col);
        __half2 h0 = __floats2half2_rn(v.x, v.y);
        __half2 h1 = __floats2half2_rn(v.z, v.w);
        uint2 p;
        p.x = *(unsigned*)&h0;
        p.y = *(unsigned*)&h1;
        *(uint2*)(dst + (size_t)(rbase + rl) * OUTF + cb + col) = p;
    }
}

// ---- gather-sum core (R12): fp16 pair-tree, fp32 across groups -------------
__device__ __forceinline__ void gather_accum(const __half* __restrict__ src,
                                             const int* __restrict__ nb,
                                             int deg, int c, float* acc) {
    int k = 0;
    for (; k + 8 <= deg; k += 8) {
        int j[8];
#pragma unroll
        for (int u = 0; u < 8; u++) j[u] = __ldg(nb + k + u);
        uint2 r[8];
#pragma unroll
        for (int u = 0; u < 8; u++)
            r[u] = *(const uint2*)(src + (size_t)j[u] * OUTF + c);
        __half2 sx01 = __hadd2(H2REF(r[0].x), H2REF(r[1].x));
        __half2 sy01 = __hadd2(H2REF(r[0].y), H2REF(r[1].y));
        __half2 sx23 = __hadd2(H2REF(r[2].x), H2REF(r[3].x));
        __half2 sy23 = __hadd2(H2REF(r[2].y), H2REF(r[3].y));
        __half2 sx45 = __hadd2(H2REF(r[4].x), H2REF(r[5].x));
        __half2 sy45 = __hadd2(H2REF(r[4].y), H2REF(r[5].y));
        __half2 sx67 = __hadd2(H2REF(r[6].x), H2REF(r[7].x));
        __half2 sy67 = __hadd2(H2REF(r[6].y), H2REF(r[7].y));
        __half2 tx0 = __hadd2(sx01, sx23);
        __half2 ty0 = __hadd2(sy01, sy23);
        __half2 tx1 = __hadd2(sx45, sx67);
        __half2 ty1 = __hadd2(sy45, sy67);
        float2 f;
        f = __half22float2(tx0); acc[0] += f.x; acc[1] += f.y;
        f = __half22float2(ty0); acc[2] += f.x; acc[3] += f.y;
        f = __half22float2(tx1); acc[0] += f.x; acc[1] += f.y;
        f = __half22float2(ty1); acc[2] += f.x; acc[3] += f.y;
    }
    for (; k < deg; k++) {
        int j = __ldg(nb + k);
        uint2 rv = *(const uint2*)(src + (size_t)j * OUTF + c);
        float2 f0 = __half22float2(H2REF(rv.x));
        float2 f1 = __half22float2(H2REF(rv.y));
        acc[0] += f0.x; acc[1] += f0.y; acc[2] += f1.x; acc[3] += f1.y;
    }
}

// ---- SpMM 128-col half: warp per (row, col-half), degree-sorted rows -------
__device__ __forceinline__ void spmm128(const __half* __restrict__ src,
                                        __half* __restrict__ dst,
                                        int blk, int ch) {
    int wid  = threadIdx.x >> 5;
    int lane = threadIdx.x & 31;
    int row  = g_perm[blk * 8 + wid];
    int deg  = g_deg[row];
    const int* __restrict__ nb = g_nbr + (size_t)row * MAXD;

    int c = ch * 128 + (lane << 2);
    float acc[4] = {0.f, 0.f, 0.f, 0.f};
    gather_accum(src, nb, deg, c, acc);

    uint2 packed;
    __half2 h0 = __floats2half2_rn(acc[0], acc[1]);
    __half2 h1 = __floats2half2_rn(acc[2], acc[3]);
    packed.x = *(unsigned*)&h0;
    packed.y = *(unsigned*)&h1;
    *(uint2*)(dst + (size_t)row * OUTF + c) = packed;
}

// ---- routed-output body (degree-sorted rows) -------------------------------
__device__ __forceinline__ void out_body(int blk, int ch, int sel,
                                         const float* __restrict__ bias,
                                         float* __restrict__ out) {
    int wid  = threadIdx.x >> 5;
    int lane = threadIdx.x & 31;
    int row  = g_perm[blk * 8 + wid];
    if (g_mask1[row] != sel) return;
    int deg  = g_deg[row];
    const int* __restrict__ nb = g_nbr + (size_t)row * MAXD;
    const __half* __restrict__ src = sel ? g_v : g_z2;

    int c = ch * 128 + (lane << 2);
    float acc[4] = {0.f, 0.f, 0.f, 0.f};
    gather_accum(src, nb, deg, c, acc);

    float4 b0 = *(const float4*)(bias + c);
    *(float4*)(out + (size_t)row * OUTF + c) =
        make_float4(acc[0] + b0.x, acc[1] + b0.y, acc[2] + b0.z, acc[3] + b0.w);
}

// ---- L2: dense GEMMs u,v [0,256) | gat1 [256,768) | perm sort [768] --------
__global__ void k_gemm_gat1(const float* __restrict__ W2, const float* __restrict__ a2) {
    int b = blockIdx.x;
    if (b < 256) {
        int which = b >> 7;
        int tile  = b & 127;
        gemm_dense(which, tile >> 1, tile & 1);
    } else if (b < 768) {
        gat1_body(b - 256, W2, a2);
    } else {
        perm_body();
    }
}

// ---- L3: z1 = A@u [0,1024) | mask [1024,1536) ------------------------------
__global__ void __launch_bounds__(256, 8)
k_z1_mask() {
    int b = blockIdx.x;
    if (b < 1024) spmm128(g_u, g_z1, b >> 1, b & 1);
    else          mask_body(b - 1024);
}

// ---- L4: z2 = A@z1 [0,1024) | out(mask1) [1024,2048) -----------------------
__global__ void __launch_bounds__(256, 8)
k_z2_out1(const float* __restrict__ bias, float* __restrict__ out) {
    int b = blockIdx.x;
    if (b < 1024) spmm128(g_z1, g_z2, b >> 1, b & 1);
    else {
        int bb = b - 1024;
        out_body(bb >> 1, bb & 1, 1, bias, out);
    }
}

// ---- L5: out(mask0) (needs z2) ---------------------------------------------
__global__ void __launch_bounds__(256, 8)
k_out0(const float* __restrict__ bias, float* __restrict__ out) {
    out_body(blockIdx.x, blockIdx.y, 0, bias, out);
}

// ---------------- launcher --------------------------------------------------
extern "C" void kernel_launch(void* const* d_in, const int* in_sizes, int n_in,
                              void* d_out, int out_size) {
    const float* x    = (const float*)d_in[0];
    const float* adj  = (const float*)d_in[1];
    const float* W1   = (const float*)d_in[2];
    const float* a1   = (const float*)d_in[3];
    const float* W2   = (const float*)d_in[4];
    const float* a2   = (const float*)d_in[5];
    const float* Wsgc = (const float*)d_in[6];
    const float* bsgc = (const float*)d_in[7];
    float* out = (float*)d_out;

    k_prelude<<<6912, 256>>>(adj, x, W1, a1, Wsgc);
    k_gemm_gat1<<<769, 256>>>(W2, a2);          // v,u GEMMs || gat1 || perm
    k_z1_mask<<<1536, 256>>>();                 // z1 = A@u || mask
    k_z2_out1<<<2048, 256>>>(bsgc, out);        // z2 = A@z1 || out(mask1)
    k_out0<<<dim3(512, 2), 256>>>(bsgc, out);   // out(mask0)
}

// round 17
// speedup vs baseline: 1.6129x; 1.0005x over previous
#include <cuda_runtime.h>
#include <cuda_fp16.h>
#include <mma.h>
#include <math.h>

using namespace nvcuda;

#define NN    4096
#define INF_  512
#define HID   8
#define OUTF  256
#define MAXD  128

#define H2REF(u) (*(__half2*)&(u))

// ---------------- scratch (static device globals) ---------------------------
__device__ int    g_deg[NN];
__device__ int    g_nbr[NN * MAXD];
__device__ int    g_perm[NN];         // rows in descending-degree order
__device__ float  g_phu[NN * HID];
__device__ float  g_e1[NN];
__device__ float  g_qu[NN];
__device__ float  g_e2[NN];
__device__ int    g_mask1[NN];
__device__ __half g_xh[NN * INF_];
__device__ __half g_v [NN * OUTF];    // x @ W_A
__device__ __half g_u [NN * OUTF];    // x @ W_C
__device__ __half g_z1[NN * OUTF];    // A @ u
__device__ __half g_z2[NN * OUTF];    // A^2 @ u
__device__ __half g_WhA[INF_ * OUTF];
__device__ __half g_WhC[INF_ * OUTF];

// ---- fused prelude: build nbr lists | x->fp16 | h=x@W1 chain | W->fp16 -----
__global__ void k_prelude(const float* __restrict__ adj, const float* __restrict__ x,
                          const float* __restrict__ W1, const float* __restrict__ a1,
                          const float* __restrict__ Wsgc) {
    int b = blockIdx.x;
    int t = threadIdx.x;          // 256

    if (b < 4096) {
        int row  = b;
        int lane = t & 31;
        int warp = t >> 5;
        const float4* ar = (const float4*)(adj + (size_t)row * NN);
        float4 v[4];
        int cnt = 0;
#pragma unroll
        for (int i = 0; i < 4; i++) {
            v[i] = ar[t + i * 256];
            cnt += (v[i].x != 0.f) + (v[i].y != 0.f) + (v[i].z != 0.f) + (v[i].w != 0.f);
        }
        // warp-level inclusive scan (sync-free)
        int pre = cnt;
#pragma unroll
        for (int o = 1; o < 32; o <<= 1) {
            int vv = __shfl_up_sync(0xffffffffu, pre, o);
            if (lane >= o) pre += vv;
        }
        __shared__ int wtot[8];
        if (lane == 31) wtot[warp] = pre;
        __syncthreads();
        int woff = 0, total = 0;
#pragma unroll
        for (int w = 0; w < 8; w++) {
            int wt = wtot[w];
            if (w < warp) woff += wt;
            total += wt;
        }
        int pos = woff + pre - cnt;       // exclusive prefix across block

        int* nb = g_nbr + (size_t)row * MAXD;
#pragma unroll
        for (int i = 0; i < 4; i++) {
            int base = (t + i * 256) * 4;
            if (v[i].x != 0.f) { if (pos < MAXD) nb[pos] = base + 0; pos++; }
            if (v[i].y != 0.f) { if (pos < MAXD) nb[pos] = base + 1; pos++; }
            if (v[i].z != 0.f) { if (pos < MAXD) nb[pos] = base + 2; pos++; }
            if (v[i].w != 0.f) { if (pos < MAXD) nb[pos] = base + 3; pos++; }
        }
        if (t == 0) g_deg[row] = total < MAXD ? total : MAXD;
    } else if (b < 6144) {
        int i = (b - 4096) * 256 + t;
        float4 v = ((const float4*)x)[i];
        __half2 lo = __floats2half2_rn(v.x, v.y);
        __half2 hi = __floats2half2_rn(v.z, v.w);
        uint2 packed;
        packed.x = *(unsigned*)&lo;
        packed.y = *(unsigned*)&hi;
        ((uint2*)g_xh)[i] = packed;
    } else if (b < 6656) {
        int lane = t & 31;
        int row  = (b - 6144) * 8 + (t >> 5);
        const float* xr = x + (size_t)row * INF_;
        float acc[HID];
#pragma unroll
        for (int f = 0; f < HID; f++) acc[f] = 0.f;
        for (int k = lane; k < INF_; k += 32) {
            float xv = xr[k];
            float4 wA = *(const float4*)(W1 + k * HID);
            float4 wB = *(const float4*)(W1 + k * HID + 4);
            acc[0] += xv * wA.x; acc[1] += xv * wA.y; acc[2] += xv * wA.z; acc[3] += xv * wA.w;
            acc[4] += xv * wB.x; acc[5] += xv * wB.y; acc[6] += xv * wB.z; acc[7] += xv * wB.w;
        }
#pragma unroll
        for (int f = 0; f < HID; f++)
            for (int o = 16; o; o >>= 1) acc[f] += __shfl_xor_sync(0xffffffffu, acc[f], o);
        if (lane == 0) {
            float d = 0.f;
#pragma unroll
            for (int f = 0; f < HID; f++) d += acc[f] * a1[HID + f];
            float e1 = expf(d);
            g_e1[row] = e1;
#pragma unroll
            for (int f = 0; f < HID; f++) g_phu[row * HID + f] = e1 * acc[f];
        }
    } else {
        int which = (b >= 6784);
        int base  = which ? 6784 : 6656;
        const float* src = Wsgc + (which ? (size_t)1024 * OUTF : 0);
        __half* dst = which ? g_WhC : g_WhA;
        int i = (b - base) * 256 + t;
        float4 v = ((const float4*)src)[i];
        __half2 lo = __floats2half2_rn(v.x, v.y);
        __half2 hi = __floats2half2_rn(v.z, v.w);
        uint2 packed;
        packed.x = *(unsigned*)&lo;
        packed.y = *(unsigned*)&hi;
        ((uint2*)dst)[i] = packed;
    }
}

// ---- block-redundant sum of 4096 floats (deterministic order) --------------
__device__ __forceinline__ float block_sum4096(const float* v, int t) {
    __shared__ float sred[8];
    __shared__ float sbc;
    float s = 0.f;
    const float4* v4 = (const float4*)v;
#pragma unroll
    for (int i = 0; i < 4; i++) {
        float4 a = v4[t + i * 256];
        s += (a.x + a.y) + (a.z + a.w);
    }
    for (int o = 16; o; o >>= 1) s += __shfl_xor_sync(0xffffffffu, s, o);
    if ((t & 31) == 0) sred[t >> 5] = s;
    __syncthreads();
    if (t < 32) {
        float r = (t < 8) ? sred[t] : 0.f;
        for (int o = 4; o; o >>= 1) r += __shfl_xor_sync(0xffffffffu, r, o);
        if (t == 0) sbc = r;
    }
    __syncthreads();
    return sbc;
}

// ---- gat1 body -------------------------------------------------------------
__device__ __forceinline__ void gat1_body(int blk, const float* __restrict__ W2,
                                          const float* __restrict__ a2) {
    int t    = threadIdx.x;
    float S1 = block_sum4096(g_e1, t);

    int lane = t & 31;
    int row  = blk * 8 + (t >> 5);
    int deg  = g_deg[row];
    const int* nb = g_nbr + (size_t)row * MAXD;

    float acc[HID];
#pragma unroll
    for (int f = 0; f < HID; f++) acc[f] = 0.f;

    for (int k = lane; k < deg; k += 32) {
        int j = nb[k];
        float4 A = *(const float4*)(g_phu + j * HID);
        float4 B = *(const float4*)(g_phu + j * HID + 4);
        acc[0] += A.x; acc[1] += A.y; acc[2] += A.z; acc[3] += A.w;
        acc[4] += B.x; acc[5] += B.y; acc[6] += B.z; acc[7] += B.w;
    }
#pragma unroll
    for (int f = 0; f < HID; f++)
        for (int o = 16; o; o >>= 1) acc[f] += __shfl_xor_sync(0xffffffffu, acc[f], o);

    if (lane == 0) {
        float invS = 1.f / S1;
        float h2 = 0.f;
#pragma unroll
        for (int f = 0; f < HID; f++) {
            float v = acc[f] * invS;
            v = v > 0.f ? v : (expf(v) - 1.f);   // elu
            h2 += v * W2[f];
        }
        float e2 = expf(h2 * a2[1]);
        g_e2[row] = e2;
        g_qu[row] = e2 * h2;
    }
}

// ---- mask body -------------------------------------------------------------
__device__ __forceinline__ void mask_body(int blk) {
    int t    = threadIdx.x;
    float S2 = block_sum4096(g_e2, t);

    int lane = t & 31;
    int row  = blk * 8 + (t >> 5);
    int deg  = g_deg[row];
    const int* nb = g_nbr + (size_t)row * MAXD;

    float s = 0.f;
    for (int k = lane; k < deg; k += 32) s += g_qu[nb[k]];
    for (int o = 16; o; o >>= 1) s += __shfl_xor_sync(0xffffffffu, s, o);

    if (lane == 0) {
        float s2 = s / S2;
        float sc = s2 > 0.f ? s2 : (expf(s2) - 1.f);   // elu
        g_mask1[row] = (sc > 0.7f) ? 1 : 0;
    }
}

// ---- perm body: counting-sort rows by descending degree --------------------
__device__ __forceinline__ void perm_body() {
    __shared__ int hist[MAXD + 1];
    __shared__ int off[MAXD + 1];
    int t = threadIdx.x;   // 256
    if (t <= MAXD) hist[t] = 0;
    __syncthreads();
    for (int r = t; r < NN; r += 256) atomicAdd(&hist[g_deg[r]], 1);
    __syncthreads();
    if (t == 0) {
        int s = 0;
        for (int d = MAXD; d >= 0; d--) { off[d] = s; s += hist[d]; }
    }
    __syncthreads();
    for (int r = t; r < NN; r += 256) {
        int pos = atomicAdd(&off[g_deg[r]], 1);
        g_perm[pos] = r;
    }
}

// ---- dense GEMM body: dst[4096x256] = xh @ Wh (fp16 out, fp32 acc) ---------
#define GLDA_S 72
#define GLDB_S 136
#define GLDS_F 132

__device__ __forceinline__ void gemm_dense(int which, int bx, int by) {
    __shared__ __align__(16) char buf[64 * GLDS_F * 4];

    __half* sA = (__half*)buf;
    __half* sB = (__half*)(buf + 64 * GLDA_S * 2);
    float*  stage = (float*)buf;

    const __half* W   = which ? g_WhC : g_WhA;
    __half*       dst = which ? g_u   : g_v;
    int rbase = bx * 64;
    int cb    = by * 128;

    int t = threadIdx.x;   // 256
    int warp = t >> 5;
    int wrow = warp & 3;
    int wcol = warp >> 2;

    const __half* aSrc = g_xh + (size_t)(rbase + (t >> 2)) * INF_;
    int apart = t & 3;

    wmma::fragment<wmma::accumulator, 16, 16, 16, float> cfr[4];
#pragma unroll
    for (int j = 0; j < 4; j++) wmma::fill_fragment(cfr[j], 0.f);

    for (int kc = 0; kc < INF_; kc += 64) {
#pragma unroll
        for (int u = 0; u < 2; u++) {
            int chunk = apart * 2 + u;
            uint4 v = *(const uint4*)(aSrc + kc + chunk * 8);
            *(uint4*)(sA + (t >> 2) * GLDA_S + chunk * 8) = v;
        }
#pragma unroll
        for (int v4 = 0; v4 < 4; v4++) {
            int idx = v4 * 256 + t;
            int krow = idx >> 4, chunk = idx & 15;
            uint4 v = *(const uint4*)(W + (size_t)(kc + krow) * OUTF + cb + chunk * 8);
            *(uint4*)(sB + krow * GLDB_S + chunk * 8) = v;
        }
        __syncthreads();

#pragma unroll
        for (int ks = 0; ks < 4; ks++) {
            wmma::fragment<wmma::matrix_a, 16, 16, 16, __half, wmma::row_major> afr;
            wmma::load_matrix_sync(afr, sA + wrow * 16 * GLDA_S + ks * 16, GLDA_S);
#pragma unroll
            for (int j = 0; j < 4; j++) {
                wmma::fragment<wmma::matrix_b, 16, 16, 16, __half, wmma::row_major> bfr;
                wmma::load_matrix_sync(bfr, sB + ks * 16 * GLDB_S + wcol * 64 + j * 16, GLDB_S);
                wmma::mma_sync(cfr[j], afr, bfr, cfr[j]);
            }
        }
        __syncthreads();
    }

#pragma unroll
    for (int j = 0; j < 4; j++)
        wmma::store_matrix_sync(stage + wrow * 16 * GLDS_F + wcol * 64 + j * 16,
                                cfr[j], GLDS_F, wmma::mem_row_major);
    __syncthreads();

#pragma unroll
    for (int w = 0; w < 8; w++) {
        int idx = w * 256 + t;
        int rl = idx >> 5, chunk = idx & 31;
        int col = chunk * 4;
        float4 v = *(const float4*)(stage + rl * GLDS_F + col);
        __half2 h0 = __floats2half2_rn(v.x, v.y);
        __half2 h1 = __floats2half2_rn(v.z, v.w);
        uint2 p;
        p.x = *(unsigned*)&h0;
        p.y = *(unsigned*)&h1;
        *(uint2*)(dst + (size_t)(rbase + rl) * OUTF + cb + col) = p;
    }
}

// ---- gather-sum core (R12): fp16 pair-tree, fp32 across groups -------------
__device__ __forceinline__ void gather_accum(const __half* __restrict__ src,
                                             const int* __restrict__ nb,
                                             int deg, int c, float* acc) {
    int k = 0;
    for (; k + 8 <= deg; k += 8) {
        int j[8];
#pragma unroll
        for (int u = 0; u < 8; u++) j[u] = __ldg(nb + k + u);
        uint2 r[8];
#pragma unroll
        for (int u = 0; u < 8; u++)
            r[u] = *(const uint2*)(src + (size_t)j[u] * OUTF + c);
        __half2 sx01 = __hadd2(H2REF(r[0].x), H2REF(r[1].x));
        __half2 sy01 = __hadd2(H2REF(r[0].y), H2REF(r[1].y));
        __half2 sx23 = __hadd2(H2REF(r[2].x), H2REF(r[3].x));
        __half2 sy23 = __hadd2(H2REF(r[2].y), H2REF(r[3].y));
        __half2 sx45 = __hadd2(H2REF(r[4].x), H2REF(r[5].x));
        __half2 sy45 = __hadd2(H2REF(r[4].y), H2REF(r[5].y));
        __half2 sx67 = __hadd2(H2REF(r[6].x), H2REF(r[7].x));
        __half2 sy67 = __hadd2(H2REF(r[6].y), H2REF(r[7].y));
        __half2 tx0 = __hadd2(sx01, sx23);
        __half2 ty0 = __hadd2(sy01, sy23);
        __half2 tx1 = __hadd2(sx45, sx67);
        __half2 ty1 = __hadd2(sy45, sy67);
        float2 f;
        f = __half22float2(tx0); acc[0] += f.x; acc[1] += f.y;
        f = __half22float2(ty0); acc[2] += f.x; acc[3] += f.y;
        f = __half22float2(tx1); acc[0] += f.x; acc[1] += f.y;
        f = __half22float2(ty1); acc[2] += f.x; acc[3] += f.y;
    }
    for (; k < deg; k++) {
        int j = __ldg(nb + k);
        uint2 rv = *(const uint2*)(src + (size_t)j * OUTF + c);
        float2 f0 = __half22float2(H2REF(rv.x));
        float2 f1 = __half22float2(H2REF(rv.y));
        acc[0] += f0.x; acc[1] += f0.y; acc[2] += f1.x; acc[3] += f1.y;
    }
}

// ---- SpMM 128-col half: warp per (row, col-half), degree-sorted rows -------
__device__ __forceinline__ void spmm128(const __half* __restrict__ src,
                                        __half* __restrict__ dst,
                                        int blk, int ch) {
    int wid  = threadIdx.x >> 5;
    int lane = threadIdx.x & 31;
    int row  = g_perm[blk * 8 + wid];
    int deg  = g_deg[row];
    const int* __restrict__ nb = g_nbr + (size_t)row * MAXD;

    int c = ch * 128 + (lane << 2);
    float acc[4] = {0.f, 0.f, 0.f, 0.f};
    gather_accum(src, nb, deg, c, acc);

    uint2 packed;
    __half2 h0 = __floats2half2_rn(acc[0], acc[1]);
    __half2 h1 = __floats2half2_rn(acc[2], acc[3]);
    packed.x = *(unsigned*)&h0;
    packed.y = *(unsigned*)&h1;
    *(uint2*)(dst + (size_t)row * OUTF + c) = packed;
}

// ---- routed-output body (degree-sorted rows) -------------------------------
__device__ __forceinline__ void out_body(int blk, int ch, int sel,
                                         const float* __restrict__ bias,
                                         float* __restrict__ out) {
    int wid  = threadIdx.x >> 5;
    int lane = threadIdx.x & 31;
    int row  = g_perm[blk * 8 + wid];
    if (g_mask1[row] != sel) return;
    int deg  = g_deg[row];
    const int* __restrict__ nb = g_nbr + (size_t)row * MAXD;
    const __half* __restrict__ src = sel ? g_v : g_z2;

    int c = ch * 128 + (lane << 2);
    float acc[4] = {0.f, 0.f, 0.f, 0.f};
    gather_accum(src, nb, deg, c, acc);

    float4 b0 = *(const float4*)(bias + c);
    *(float4*)(out + (size_t)row * OUTF + c) =
        make_float4(acc[0] + b0.x, acc[1] + b0.y, acc[2] + b0.z, acc[3] + b0.w);
}

// ---- L2: dense GEMMs u,v [0,256) | gat1 [256,768) | perm sort [768] --------
__global__ void k_gemm_gat1(const float* __restrict__ W2, const float* __restrict__ a2) {
    int b = blockIdx.x;
    if (b < 256) {
        int which = b >> 7;
        int tile  = b & 127;
        gemm_dense(which, tile >> 1, tile & 1);
    } else if (b < 768) {
        gat1_body(b - 256, W2, a2);
    } else {
        perm_body();
    }
}

// ---- L3: z1 = A@u [0,1024) | mask [1024,1536) ------------------------------
__global__ void __launch_bounds__(256, 8)
k_z1_mask() {
    int b = blockIdx.x;
    if (b < 1024) spmm128(g_u, g_z1, b >> 1, b & 1);
    else          mask_body(b - 1024);
}

// ---- L4: z2 = A@z1 [0,1024) | out(mask1) [1024,2048) -----------------------
__global__ void __launch_bounds__(256, 8)
k_z2_out1(const float* __restrict__ bias, float* __restrict__ out) {
    int b = blockIdx.x;
    if (b < 1024) spmm128(g_z1, g_z2, b >> 1, b & 1);
    else {
        int bb = b - 1024;
        out_body(bb >> 1, bb & 1, 1, bias, out);
    }
}

// ---- L5: out(mask0) (needs z2) ---------------------------------------------
__global__ void __launch_bounds__(256, 8)
k_out0(const float* __restrict__ bias, float* __restrict__ out) {
    out_body(blockIdx.x, blockIdx.y, 0, bias, out);
}

// ---------------- launcher --------------------------------------------------
extern "C" void kernel_launch(void* const* d_in, const int* in_sizes, int n_in,
                              void* d_out, int out_size) {
    const float* x    = (const float*)d_in[0];
    const float* adj  = (const float*)d_in[1];
    const float* W1   = (const float*)d_in[2];
    const float* a1   = (const float*)d_in[3];
    const float* W2   = (const float*)d_in[4];
    const float* a2   = (const float*)d_in[5];
    const float* Wsgc = (const float*)d_in[6];
    const float* bsgc = (const float*)d_in[7];
    float* out = (float*)d_out;

    k_prelude<<<6912, 256>>>(adj, x, W1, a1, Wsgc);
    k_gemm_gat1<<<769, 256>>>(W2, a2);          // v,u GEMMs || gat1 || perm
    k_z1_mask<<<1536, 256>>>();                 // z1 = A@u || mask
    k_z2_out1<<<2048, 256>>>(bsgc, out);        // z2 = A@z1 || out(mask1)
    k_out0<<<dim3(512, 2), 256>>>(bsgc, out);   // out(mask0)
}